// round 8
// baseline (speedup 1.0000x reference)
#include <cuda_runtime.h>
#include <cuda_fp16.h>
#include <cstdint>

#define DEF 256
#define NF  4096   // DEF * HEAD
#define BSZ 4096
#define CHUNK 2048 // samples per L2-resident chunk

// f16 scratch
__device__ __half g_abf[2][(size_t)BSZ * DEF];   // drug/protein f16
__device__ __half g_wbf[2][(size_t)NF * DEF];    // W transposed [n][k] f16 (W_d pre-scaled by 1/16)
__device__ __half g_att[2][(size_t)BSZ * NF];    // relu activations f16 (drug side pre-scaled)

// ---------------------------------------------------------------------------
// helpers
// ---------------------------------------------------------------------------
__device__ __forceinline__ float tanh_fast(float x) {
    float y;
    asm("tanh.approx.f32 %0, %1;" : "=f"(y) : "f"(x));
    return y;
}
__device__ __forceinline__ __half2 tanh_h2(uint32_t v) {
    uint32_t r;
    asm("tanh.approx.f16x2 %0, %1;" : "=r"(r) : "r"(v));
    return *reinterpret_cast<__half2*>(&r);
}
__device__ __forceinline__ uint32_t smem_u32(const void* p) {
    uint32_t a;
    asm("{ .reg .u64 t; cvta.to.shared.u64 t, %1; cvt.u32.u64 %0, t; }" : "=r"(a) : "l"(p));
    return a;
}
__device__ __forceinline__ void cp16(uint32_t dst, const void* src) {
    asm volatile("cp.async.cg.shared.global [%0], [%1], 16;"
                 :: "r"(dst), "l"(__cvta_generic_to_global(src)) : "memory");
}
#define CP_COMMIT() asm volatile("cp.async.commit_group;" ::: "memory")
#define CP_WAIT(n)  asm volatile("cp.async.wait_group %0;" :: "n"(n) : "memory")

// discard a 128B L2 line (dirty data dropped, no DRAM writeback)
__device__ __forceinline__ void discard_l2(const void* p) {
    asm volatile("discard.global.L2 [%0], 128;"
                 :: "l"(__cvta_generic_to_global(p)) : "memory");
}

__device__ __forceinline__ void ldsm_x4(uint32_t (&r)[4], uint32_t addr) {
    asm volatile("ldmatrix.sync.aligned.m8n8.x4.shared.b16 {%0,%1,%2,%3}, [%4];"
                 : "=r"(r[0]), "=r"(r[1]), "=r"(r[2]), "=r"(r[3]) : "r"(addr));
}
__device__ __forceinline__ void ldsm_x4t(uint32_t (&r)[4], uint32_t addr) {
    asm volatile("ldmatrix.sync.aligned.m8n8.x4.trans.shared.b16 {%0,%1,%2,%3}, [%4];"
                 : "=r"(r[0]), "=r"(r[1]), "=r"(r[2]), "=r"(r[3]) : "r"(addr));
}
// f16 inputs, f16 accumulator, D += A*B
__device__ __forceinline__ void mma_h16_acc(uint32_t (&d)[2], const uint32_t (&a)[4],
                                            uint32_t b0, uint32_t b1) {
    asm volatile("mma.sync.aligned.m16n8k16.row.col.f16.f16.f16.f16 "
                 "{%0,%1}, {%2,%3,%4,%5}, {%6,%7}, {%0,%1};"
                 : "+r"(d[0]), "+r"(d[1])
                 : "r"(a[0]), "r"(a[1]), "r"(a[2]), "r"(a[3]), "r"(b0), "r"(b1));
}
// f16 inputs, f16 accumulator, D = A*B
__device__ __forceinline__ void mma_h16(uint32_t (&d)[2], const uint32_t (&a)[4],
                                        uint32_t b0, uint32_t b1) {
    asm volatile("mma.sync.aligned.m16n8k16.row.col.f16.f16.f16.f16 "
                 "{%0,%1}, {%2,%3,%4,%5}, {%6,%7}, {%8,%9};"
                 : "=r"(d[0]), "=r"(d[1])
                 : "r"(a[0]), "r"(a[1]), "r"(a[2]), "r"(a[3]),
                   "r"(b0), "r"(b1), "r"(0u), "r"(0u));
}
__device__ __forceinline__ __half2 shfl_h2(__half2 v, int m) {
    uint32_t u = *reinterpret_cast<uint32_t*>(&v);
    u = __shfl_xor_sync(0xffffffffu, u, m);
    return *reinterpret_cast<__half2*>(&u);
}

// ---------------------------------------------------------------------------
// Prep: blocks [0,1024): drug/protein fp32 -> f16
//       blocks [1024,3072): W[k][n] fp32 -> Wt[n][k] f16 (W_d scaled by 1/16)
// ---------------------------------------------------------------------------
__global__ __launch_bounds__(256) void prep_kernel(
    const float* __restrict__ drug, const float* __restrict__ protein,
    const float* __restrict__ Wd, const float* __restrict__ Wp)
{
    __shared__ float t[32][33];
    int bid = blockIdx.x, tid = threadIdx.x;
    if (bid < 1024) {
        int i = bid * 256 + tid;                      // < BSZ*DEF/4
        float4 v = ((const float4*)drug)[i];
        __half2* d0 = (__half2*)g_abf[0];
        d0[i * 2]     = __floats2half2_rn(v.x, v.y);
        d0[i * 2 + 1] = __floats2half2_rn(v.z, v.w);
        float4 w = ((const float4*)protein)[i];
        __half2* d1 = (__half2*)g_abf[1];
        d1[i * 2]     = __floats2half2_rn(w.x, w.y);
        d1[i * 2 + 1] = __floats2half2_rn(w.z, w.w);
        return;
    }
    int wb = bid - 1024;                              // 0..2047
    int z = wb >> 10;
    int r = wb & 1023;
    int n0 = (r & 127) * 32, k0 = (r >> 7) * 32;
    const float* W = z ? Wp : Wd;
    float scale = z ? 1.0f : 0.0625f;
    int tx = tid & 31, ty = tid >> 5;                 // (32, 8)
#pragma unroll
    for (int q = 0; q < 4; q++)
        t[ty + q * 8][tx] = W[(size_t)(k0 + ty + q * 8) * NF + n0 + tx];
    __syncthreads();
#pragma unroll
    for (int q = 0; q < 4; q++)
        g_wbf[z][(size_t)(n0 + ty + q * 8) * DEF + k0 + tx] =
            __float2half(t[tx][ty + q * 8] * scale);
}

// ---------------------------------------------------------------------------
// HMMA GEMM (f16 accumulators): g_att[z][128x128 tile] = relu(A@Wt^T + b)
// 256 thr (8 warps, warp tile 64x32). K = 4 chunks of 64, 2-stage cp.async
// pipeline, 64KB smem -> 2 CTAs/SM. Epilogue staged through smem (STG.128).
// Processes sample rows [Mb0, Mb0 + CHUNK).
// ---------------------------------------------------------------------------
#define GSMEM 65536

__global__ __launch_bounds__(256, 2) void gemm_tc_kernel(const float* __restrict__ b_d,
                                                         const float* __restrict__ b_p,
                                                         int Mb0)
{
    extern __shared__ __align__(16) char dsm[];       // stage s: A @ s*32768, B @ s*32768+16384
    __shared__ __half2 bias2[64];

    const int tid = threadIdx.x, lane = tid & 31, w = tid >> 5;
    const int wm = w >> 2, wn = w & 3;                // 2x4 warp grid
    const int Nb = blockIdx.x * 128, Mb = Mb0 + blockIdx.y * 128, z = blockIdx.z;
    uint32_t sbase = smem_u32(dsm);

    const __half* Ag = g_abf[z];
    const __half* Bg = g_wbf[z];
    if (tid < 64) {
        float s = z ? 1.0f : 0.0625f;
        const float* bias = z ? b_p : b_d;
        bias2[tid] = __floats2half2_rn(bias[Nb + 2 * tid] * s, bias[Nb + 2 * tid + 1] * s);
    }

    auto load_chunk = [&](int ch, int st) {
        uint32_t aB = sbase + st * 32768;
        uint32_t bB = aB + 16384;
#pragma unroll
        for (int j = 0; j < 4; j++) {
            int idx = tid + j * 256;                   // 0..1023
            int r = idx >> 3, c = idx & 7;
            uint32_t sw = (uint32_t)(r * 128 + ((c ^ (r & 7)) << 4));
            cp16(aB + sw, Ag + (size_t)(Mb + r) * DEF + ch * 64 + c * 8);
            cp16(bB + sw, Bg + (size_t)(Nb + r) * DEF + ch * 64 + c * 8);
        }
        CP_COMMIT();
    };

    load_chunk(0, 0);
    load_chunk(1, 1);

    uint32_t acc[4][4][2];
#pragma unroll
    for (int mf = 0; mf < 4; mf++)
#pragma unroll
        for (int nf = 0; nf < 4; nf++) { acc[mf][nf][0] = 0u; acc[mf][nf][1] = 0u; }

#pragma unroll
    for (int ch = 0; ch < 4; ch++) {
        if (ch == 3) { CP_WAIT(0); } else { CP_WAIT(1); }
        __syncthreads();
        uint32_t aBase = sbase + (ch & 1) * 32768;
        uint32_t bBase = aBase + 16384;
#pragma unroll
        for (int ks = 0; ks < 4; ks++) {
            uint32_t a[4][4];
#pragma unroll
            for (int mf = 0; mf < 4; mf++) {
                int r  = wm * 64 + mf * 16 + (lane & 7) + 8 * ((lane >> 3) & 1);
                int kc = ks * 2 + (lane >> 4);
                ldsm_x4(a[mf], aBase + r * 128 + ((kc ^ (r & 7)) << 4));
            }
            uint32_t bq[2][4];
#pragma unroll
            for (int g = 0; g < 2; g++) {
                int nr = wn * 32 + g * 16 + (lane & 7) + 8 * ((lane >> 4) & 1);
                int kc = ks * 2 + ((lane >> 3) & 1);
                ldsm_x4(bq[g], bBase + nr * 128 + ((kc ^ (nr & 7)) << 4));
            }
#pragma unroll
            for (int mf = 0; mf < 4; mf++)
#pragma unroll
                for (int nf = 0; nf < 4; nf++)
                    mma_h16_acc(acc[mf][nf], a[mf],
                                bq[nf >> 1][(nf & 1) * 2], bq[nf >> 1][(nf & 1) * 2 + 1]);
        }
        __syncthreads();
        if (ch + 2 < 4) load_chunk(ch + 2, ch & 1);
    }

    // epilogue: bias + relu in half2, staged via smem (XOR-swizzled), STG.128
    const __half2 z2 = __float2half2_rn(0.0f);
#pragma unroll
    for (int mf = 0; mf < 4; mf++) {
        int r0 = wm * 64 + mf * 16 + (lane >> 2);
#pragma unroll
        for (int nf = 0; nf < 4; nf++) {
            int u = wn * 4 + nf;                       // 16B unit within 256B row
            __half2 b2 = bias2[u * 4 + (lane & 3)];
            __half2 h0 = __hmax2(__hadd2(*(__half2*)&acc[mf][nf][0], b2), z2);
            __half2 h1 = __hmax2(__hadd2(*(__half2*)&acc[mf][nf][1], b2), z2);
            uint32_t a0 = sbase + r0 * 256 + ((u ^ (r0 & 7)) << 4) + 4 * (lane & 3);
            int r1 = r0 + 8;
            uint32_t a1 = sbase + r1 * 256 + ((u ^ (r1 & 7)) << 4) + 4 * (lane & 3);
            asm volatile("st.shared.b32 [%0], %1;" :: "r"(a0), "r"(*(uint32_t*)&h0) : "memory");
            asm volatile("st.shared.b32 [%0], %1;" :: "r"(a1), "r"(*(uint32_t*)&h1) : "memory");
        }
    }
    __syncthreads();
#pragma unroll
    for (int p = 0; p < 8; p++) {
        int g = tid + p * 256;                         // 0..2047 16B units
        int row = g >> 4, u = g & 15;
        uint4 v;
        uint32_t ad = sbase + row * 256 + ((u ^ (row & 7)) << 4);
        asm volatile("ld.shared.v4.u32 {%0,%1,%2,%3}, [%4];"
                     : "=r"(v.x), "=r"(v.y), "=r"(v.z), "=r"(v.w) : "r"(ad));
        *(uint4*)&g_att[z][(size_t)(Mb + row) * NF + Nb + u * 8] = v;
    }
}

// ---------------------------------------------------------------------------
// Interaction: per-sample S = D(scaled) @ P via f16-accumulator HMMA (K=16).
// Processes samples [b0, b0 + CHUNK); discards consumed g_att L2 lines.
// ---------------------------------------------------------------------------
__global__ __launch_bounds__(256) void interact_kernel(
    const float* __restrict__ drug, const float* __restrict__ protein,
    float* __restrict__ out, int b0)
{
    __shared__ __align__(16) char Dsm[256 * 48];      // D rows stride 48B (32B data + pad)
    __shared__ __align__(16) char Psm[16 * 512];      // P [16][256] f16, XOR-swizzled
    __shared__ __half2 colpart[8][128];
    __shared__ float rowsum[256];

    const int b = b0 + blockIdx.x, tid = threadIdx.x, lane = tid & 31, w = tid >> 5;
    uint32_t sD = smem_u32(Dsm), sP = smem_u32(Psm);
    const __half* Drow = g_att[0] + (size_t)b * NF;
    const __half* Prow = g_att[1] + (size_t)b * NF;

#pragma unroll
    for (int j = 0; j < 2; j++) {
        int idx = tid + j * 256;                       // 0..511, 16B chunks
        int r = idx >> 1, c = idx & 1;
        cp16(sD + r * 48 + c * 16, Drow + idx * 8);
        int h = idx >> 5, c2 = idx & 31;
        cp16(sP + h * 512 + ((c2 ^ (h & 7)) << 4), Prow + idx * 8);
    }
    CP_COMMIT(); CP_WAIT(0); __syncthreads();

    // drop this CTA's g_att lines from L2 (no DRAM writeback; data is scratch)
    if (tid < 64)       discard_l2((const char*)Drow + tid * 128);
    else if (tid < 128) discard_l2((const char*)Prow + (tid - 64) * 128);

    uint32_t a[2][4];
#pragma unroll
    for (int mf = 0; mf < 2; mf++) {
        int r  = w * 32 + mf * 16 + (lane & 7) + 8 * ((lane >> 3) & 1);
        int kc = lane >> 4;
        ldsm_x4(a[mf], sD + r * 48 + kc * 16);
    }

    __half2 zero2 = __float2half2_rn(0.0f);
    __half2 rowp[4] = {zero2, zero2, zero2, zero2};

#pragma unroll
    for (int it = 0; it < 16; it++) {
        int n0 = it * 16;
        uint32_t bq[4];
        {
            int h = (lane & 7) + 8 * ((lane >> 3) & 1);
            int n = n0 + 8 * (lane >> 4);
            ldsm_x4t(bq, sP + h * 512 + (((n >> 3) ^ (h & 7)) << 4));
        }
        __half2 cp0 = zero2, cp1 = zero2;
#pragma unroll
        for (int mf = 0; mf < 2; mf++) {
            uint32_t d0[2];
            mma_h16(d0, a[mf], bq[0], bq[1]);          // cols n0 + 2q
            __half2 tA = tanh_h2(d0[0]);
            __half2 tB = tanh_h2(d0[1]);
            rowp[mf * 2 + 0] = __hadd2(rowp[mf * 2 + 0], tA);
            rowp[mf * 2 + 1] = __hadd2(rowp[mf * 2 + 1], tB);
            cp0 = __hadd2(cp0, __hadd2(tA, tB));

            uint32_t d1[2];
            mma_h16(d1, a[mf], bq[2], bq[3]);          // cols n0 + 8 + 2q
            tA = tanh_h2(d1[0]);
            tB = tanh_h2(d1[1]);
            rowp[mf * 2 + 0] = __hadd2(rowp[mf * 2 + 0], tA);
            rowp[mf * 2 + 1] = __hadd2(rowp[mf * 2 + 1], tB);
            cp1 = __hadd2(cp1, __hadd2(tA, tB));
        }
        cp0 = __hadd2(cp0, shfl_h2(cp0, 4));
        cp0 = __hadd2(cp0, shfl_h2(cp0, 8));
        cp0 = __hadd2(cp0, shfl_h2(cp0, 16));
        cp1 = __hadd2(cp1, shfl_h2(cp1, 4));
        cp1 = __hadd2(cp1, shfl_h2(cp1, 8));
        cp1 = __hadd2(cp1, shfl_h2(cp1, 16));
        if (lane < 4) {
            colpart[w][(n0 >> 1) + lane]     = cp0;
            colpart[w][(n0 >> 1) + 4 + lane] = cp1;
        }
    }

#pragma unroll
    for (int s = 0; s < 4; s++) {
        __half2 v = rowp[s];
        v = __hadd2(v, shfl_h2(v, 1));
        v = __hadd2(v, shfl_h2(v, 2));
        if ((lane & 3) == 0) {
            int row = w * 32 + (s >> 1) * 16 + (s & 1) * 8 + (lane >> 2);
            rowsum[row] = __low2float(v) + __high2float(v);
        }
    }
    __syncthreads();

    size_t o = (size_t)b * DEF + tid;
    out[o] = drug[o] * tanh_fast(rowsum[tid]);

    if (tid < 128) {
        float c0 = 0.0f, c1 = 0.0f;
#pragma unroll
        for (int ww = 0; ww < 8; ww++) {
            __half2 v = colpart[ww][tid];
            c0 += __low2float(v);
            c1 += __high2float(v);
        }
        size_t base2 = (size_t)BSZ * DEF + (size_t)b * DEF + 2 * tid;
        out[base2]     = protein[(size_t)b * DEF + 2 * tid]     * tanh_fast(c0);
        out[base2 + 1] = protein[(size_t)b * DEF + 2 * tid + 1] * tanh_fast(c1);
    }
}

// ---------------------------------------------------------------------------
extern "C" void kernel_launch(void* const* d_in, const int* in_sizes, int n_in,
                              void* d_out, int out_size)
{
    const float* drug    = (const float*)d_in[0];
    const float* protein = (const float*)d_in[1];
    const float* W_d     = (const float*)d_in[2];
    const float* b_d     = (const float*)d_in[3];
    const float* W_p     = (const float*)d_in[4];
    const float* b_p     = (const float*)d_in[5];
    float* out = (float*)d_out;

    cudaFuncSetAttribute(gemm_tc_kernel, cudaFuncAttributeMaxDynamicSharedMemorySize, GSMEM);

    prep_kernel<<<3072, 256>>>(drug, protein, W_d, W_p);
    for (int c = 0; c < BSZ / CHUNK; c++) {
        gemm_tc_kernel<<<dim3(NF / 128, CHUNK / 128, 2), 256, GSMEM>>>(b_d, b_p, c * CHUNK);
        interact_kernel<<<CHUNK, 256>>>(drug, protein, out, c * CHUNK);
    }
}

// round 9
// speedup vs baseline: 1.0081x; 1.0081x over previous
#include <cuda_runtime.h>
#include <cuda_fp16.h>
#include <cstdint>

#define DEF 256
#define NF  4096   // DEF * HEAD
#define BSZ 4096

// f16 scratch
__device__ __half g_abf[2][(size_t)BSZ * DEF];   // drug/protein f16
__device__ __half g_wbf[2][(size_t)NF * DEF];    // W transposed [n][k] f16 (W_d pre-scaled by 1/16)
__device__ __half g_att[2][(size_t)BSZ * NF];    // relu activations f16 (drug side pre-scaled)

// ---------------------------------------------------------------------------
// helpers
// ---------------------------------------------------------------------------
__device__ __forceinline__ float tanh_fast(float x) {
    float y;
    asm("tanh.approx.f32 %0, %1;" : "=f"(y) : "f"(x));
    return y;
}
__device__ __forceinline__ uint32_t tanh_h2u(uint32_t v) {
    uint32_t r;
    asm("tanh.approx.f16x2 %0, %1;" : "=r"(r) : "r"(v));
    return r;
}
__device__ __forceinline__ uint32_t smem_u32(const void* p) {
    uint32_t a;
    asm("{ .reg .u64 t; cvta.to.shared.u64 t, %1; cvt.u32.u64 %0, t; }" : "=r"(a) : "l"(p));
    return a;
}
__device__ __forceinline__ void cp16(uint32_t dst, const void* src) {
    asm volatile("cp.async.cg.shared.global [%0], [%1], 16;"
                 :: "r"(dst), "l"(__cvta_generic_to_global(src)) : "memory");
}
#define CP_COMMIT() asm volatile("cp.async.commit_group;" ::: "memory")
#define CP_WAIT(n)  asm volatile("cp.async.wait_group %0;" :: "n"(n) : "memory")

__device__ __forceinline__ void discard_l2(const void* p) {
    asm volatile("discard.global.L2 [%0], 128;"
                 :: "l"(__cvta_generic_to_global(p)) : "memory");
}

__device__ __forceinline__ void ldsm_x4(uint32_t (&r)[4], uint32_t addr) {
    asm volatile("ldmatrix.sync.aligned.m8n8.x4.shared.b16 {%0,%1,%2,%3}, [%4];"
                 : "=r"(r[0]), "=r"(r[1]), "=r"(r[2]), "=r"(r[3]) : "r"(addr));
}
__device__ __forceinline__ void ldsm_x4t(uint32_t (&r)[4], uint32_t addr) {
    asm volatile("ldmatrix.sync.aligned.m8n8.x4.trans.shared.b16 {%0,%1,%2,%3}, [%4];"
                 : "=r"(r[0]), "=r"(r[1]), "=r"(r[2]), "=r"(r[3]) : "r"(addr));
}
// f16 inputs, f16 accumulator, D += A*B
__device__ __forceinline__ void mma_h16_acc(uint32_t (&d)[2], const uint32_t (&a)[4],
                                            uint32_t b0, uint32_t b1) {
    asm volatile("mma.sync.aligned.m16n8k16.row.col.f16.f16.f16.f16 "
                 "{%0,%1}, {%2,%3,%4,%5}, {%6,%7}, {%0,%1};"
                 : "+r"(d[0]), "+r"(d[1])
                 : "r"(a[0]), "r"(a[1]), "r"(a[2]), "r"(a[3]), "r"(b0), "r"(b1));
}
// f16 inputs, f16 accumulator, D = A*B
__device__ __forceinline__ void mma_h16(uint32_t (&d)[2], const uint32_t (&a)[4],
                                        uint32_t b0, uint32_t b1) {
    asm volatile("mma.sync.aligned.m16n8k16.row.col.f16.f16.f16.f16 "
                 "{%0,%1}, {%2,%3,%4,%5}, {%6,%7}, {%8,%9};"
                 : "=r"(d[0]), "=r"(d[1])
                 : "r"(a[0]), "r"(a[1]), "r"(a[2]), "r"(a[3]),
                   "r"(b0), "r"(b1), "r"(0u), "r"(0u));
}
__device__ __forceinline__ __half2 shfl_h2(__half2 v, int m) {
    uint32_t u = *reinterpret_cast<uint32_t*>(&v);
    u = __shfl_xor_sync(0xffffffffu, u, m);
    return *reinterpret_cast<__half2*>(&u);
}

// ---------------------------------------------------------------------------
// Prep: blocks [0,1024): drug/protein fp32 -> f16
//       blocks [1024,3072): W[k][n] fp32 -> Wt[n][k] f16 (W_d scaled by 1/16)
// ---------------------------------------------------------------------------
__global__ __launch_bounds__(256) void prep_kernel(
    const float* __restrict__ drug, const float* __restrict__ protein,
    const float* __restrict__ Wd, const float* __restrict__ Wp)
{
    __shared__ float t[32][33];
    int bid = blockIdx.x, tid = threadIdx.x;
    if (bid < 1024) {
        int i = bid * 256 + tid;                      // < BSZ*DEF/4
        float4 v = ((const float4*)drug)[i];
        __half2* d0 = (__half2*)g_abf[0];
        d0[i * 2]     = __floats2half2_rn(v.x, v.y);
        d0[i * 2 + 1] = __floats2half2_rn(v.z, v.w);
        float4 w = ((const float4*)protein)[i];
        __half2* d1 = (__half2*)g_abf[1];
        d1[i * 2]     = __floats2half2_rn(w.x, w.y);
        d1[i * 2 + 1] = __floats2half2_rn(w.z, w.w);
        return;
    }
    int wb = bid - 1024;                              // 0..2047
    int z = wb >> 10;
    int r = wb & 1023;
    int n0 = (r & 127) * 32, k0 = (r >> 7) * 32;
    const float* W = z ? Wp : Wd;
    float scale = z ? 1.0f : 0.0625f;
    int tx = tid & 31, ty = tid >> 5;                 // (32, 8)
#pragma unroll
    for (int q = 0; q < 4; q++)
        t[ty + q * 8][tx] = W[(size_t)(k0 + ty + q * 8) * NF + n0 + tx];
    __syncthreads();
#pragma unroll
    for (int q = 0; q < 4; q++)
        g_wbf[z][(size_t)(n0 + ty + q * 8) * DEF + k0 + tx] =
            __float2half(t[tx][ty + q * 8] * scale);
}

// ---------------------------------------------------------------------------
// HMMA GEMM (f16 acc): CTA tile 128x256, warp tile 64x64 (2x4 warp grid).
// K = 4 chunks of 64, 2-stage cp.async pipeline, 96KB smem -> 2 CTAs/SM.
// 8 LDSM per 32 MMA per ks step. Epilogue staged through smem, STG.128.
// ---------------------------------------------------------------------------
#define GSMEM (2 * 49152)   // 96KB; epilogue C staging (64KB) reuses stage space

__global__ __launch_bounds__(256, 2) void gemm_tc_kernel(const float* __restrict__ b_d,
                                                         const float* __restrict__ b_p)
{
    extern __shared__ __align__(16) char dsm[];  // stage s: A @ s*49152 (16KB), B @ +16384 (32KB)
    __shared__ __half2 bias2[128];

    const int tid = threadIdx.x, lane = tid & 31, w = tid >> 5;
    const int wm = w >> 2, wn = w & 3;                // 2x4 warp grid
    const int Nb = blockIdx.x * 256, Mb = blockIdx.y * 128, z = blockIdx.z;
    uint32_t sbase = smem_u32(dsm);

    const __half* Ag = g_abf[z];
    const __half* Bg = g_wbf[z];
    if (tid < 128) {
        float s = z ? 1.0f : 0.0625f;
        const float* bias = z ? b_p : b_d;
        bias2[tid] = __floats2half2_rn(bias[Nb + 2 * tid] * s, bias[Nb + 2 * tid + 1] * s);
    }

    auto load_chunk = [&](int ch, int st) {
        uint32_t aB = sbase + st * 49152;
        uint32_t bB = aB + 16384;
#pragma unroll
        for (int j = 0; j < 4; j++) {                  // A: 128 rows x 64 cols
            int idx = tid + j * 256;                   // 0..1023
            int r = idx >> 3, c = idx & 7;
            uint32_t sw = (uint32_t)(r * 128 + ((c ^ (r & 7)) << 4));
            cp16(aB + sw, Ag + (size_t)(Mb + r) * DEF + ch * 64 + c * 8);
        }
#pragma unroll
        for (int j = 0; j < 8; j++) {                  // B: 256 rows x 64 cols
            int idx = tid + j * 256;                   // 0..2047
            int r = idx >> 3, c = idx & 7;
            uint32_t sw = (uint32_t)(r * 128 + ((c ^ (r & 7)) << 4));
            cp16(bB + sw, Bg + (size_t)(Nb + r) * DEF + ch * 64 + c * 8);
        }
        CP_COMMIT();
    };

    load_chunk(0, 0);
    load_chunk(1, 1);

    uint32_t acc[4][8][2];
#pragma unroll
    for (int mf = 0; mf < 4; mf++)
#pragma unroll
        for (int nf = 0; nf < 8; nf++) { acc[mf][nf][0] = 0u; acc[mf][nf][1] = 0u; }

#pragma unroll
    for (int ch = 0; ch < 4; ch++) {
        if (ch == 3) { CP_WAIT(0); } else { CP_WAIT(1); }
        __syncthreads();
        uint32_t aBase = sbase + (ch & 1) * 49152;
        uint32_t bBase = aBase + 16384;
#pragma unroll
        for (int ks = 0; ks < 4; ks++) {
            uint32_t a[4][4];
#pragma unroll
            for (int mf = 0; mf < 4; mf++) {
                int r  = wm * 64 + mf * 16 + (lane & 7) + 8 * ((lane >> 3) & 1);
                int kc = ks * 2 + (lane >> 4);
                ldsm_x4(a[mf], aBase + r * 128 + ((kc ^ (r & 7)) << 4));
            }
            uint32_t bq[4][4];
#pragma unroll
            for (int g = 0; g < 4; g++) {
                int nr = wn * 64 + g * 16 + (lane & 7) + 8 * ((lane >> 4) & 1);
                int kc = ks * 2 + ((lane >> 3) & 1);
                ldsm_x4(bq[g], bBase + nr * 128 + ((kc ^ (nr & 7)) << 4));
            }
#pragma unroll
            for (int mf = 0; mf < 4; mf++)
#pragma unroll
                for (int nf = 0; nf < 8; nf++)
                    mma_h16_acc(acc[mf][nf], a[mf],
                                bq[nf >> 1][(nf & 1) * 2], bq[nf >> 1][(nf & 1) * 2 + 1]);
        }
        __syncthreads();
        if (ch + 2 < 4) load_chunk(ch + 2, ch & 1);
    }

    // epilogue: bias + relu in half2, staged via smem (XOR swizzle, conflict-free)
    const __half2 z2 = __float2half2_rn(0.0f);
#pragma unroll
    for (int mf = 0; mf < 4; mf++) {
        int r0 = wm * 64 + mf * 16 + (lane >> 2);
        int r1 = r0 + 8;
#pragma unroll
        for (int nf = 0; nf < 8; nf++) {
            int u = wn * 8 + nf;                       // 16B unit within 512B row (0..31)
            __half2 b2 = bias2[u * 4 + (lane & 3)];
            __half2 h0 = __hmax2(__hadd2(*(__half2*)&acc[mf][nf][0], b2), z2);
            __half2 h1 = __hmax2(__hadd2(*(__half2*)&acc[mf][nf][1], b2), z2);
            uint32_t a0 = sbase + r0 * 512 + ((u ^ (r0 & 7)) << 4) + 4 * (lane & 3);
            uint32_t a1 = sbase + r1 * 512 + ((u ^ (r1 & 7)) << 4) + 4 * (lane & 3);
            asm volatile("st.shared.b32 [%0], %1;" :: "r"(a0), "r"(*(uint32_t*)&h0) : "memory");
            asm volatile("st.shared.b32 [%0], %1;" :: "r"(a1), "r"(*(uint32_t*)&h1) : "memory");
        }
    }
    __syncthreads();
#pragma unroll
    for (int p = 0; p < 16; p++) {
        int g = tid + p * 256;                         // 0..4095 16B units
        int row = g >> 5, u = g & 31;
        uint4 v;
        uint32_t ad = sbase + row * 512 + ((u ^ (row & 7)) << 4);
        asm volatile("ld.shared.v4.u32 {%0,%1,%2,%3}, [%4];"
                     : "=r"(v.x), "=r"(v.y), "=r"(v.z), "=r"(v.w) : "r"(ad));
        *(uint4*)&g_att[z][(size_t)(Mb + row) * NF + Nb + u * 8] = v;
    }
}

// ---------------------------------------------------------------------------
// Interaction: per-sample S = D(scaled) @ P via f16-acc HMMA (K=16).
// Row sums computed ON THE TENSOR PIPE: tanh results (C-fragment layout ==
// A-fragment layout) feed a second MMA with B = ones.
// ---------------------------------------------------------------------------
__global__ __launch_bounds__(256) void interact_kernel(
    const float* __restrict__ drug, const float* __restrict__ protein,
    float* __restrict__ out)
{
    __shared__ __align__(16) char Dsm[256 * 48];      // D rows stride 48B (32B data + pad)
    __shared__ __align__(16) char Psm[16 * 512];      // P [16][256] f16, XOR-swizzled
    __shared__ __half2 colpart[8][128];
    __shared__ float rowsum[256];

    const int b = blockIdx.x, tid = threadIdx.x, lane = tid & 31, w = tid >> 5;
    uint32_t sD = smem_u32(Dsm), sP = smem_u32(Psm);
    const __half* Drow = g_att[0] + (size_t)b * NF;
    const __half* Prow = g_att[1] + (size_t)b * NF;

#pragma unroll
    for (int j = 0; j < 2; j++) {
        int idx = tid + j * 256;                       // 0..511, 16B chunks
        int r = idx >> 1, c = idx & 1;
        cp16(sD + r * 48 + c * 16, Drow + idx * 8);
        int h = idx >> 5, c2 = idx & 31;
        cp16(sP + h * 512 + ((c2 ^ (h & 7)) << 4), Prow + idx * 8);
    }
    CP_COMMIT(); CP_WAIT(0); __syncthreads();

    // drop consumed g_att lines from L2 (scratch; avoids DRAM writeback)
    if (tid < 64)       discard_l2((const char*)Drow + tid * 128);
    else if (tid < 128) discard_l2((const char*)Prow + (tid - 64) * 128);

    uint32_t a[2][4];
#pragma unroll
    for (int mf = 0; mf < 2; mf++) {
        int r  = w * 32 + mf * 16 + (lane & 7) + 8 * ((lane >> 3) & 1);
        int kc = lane >> 4;
        ldsm_x4(a[mf], sD + r * 48 + kc * 16);
    }

    const uint32_t ONES = 0x3C003C00u;                 // (1.0h, 1.0h)
    const __half2 zero2 = __float2half2_rn(0.0f);
    uint32_t rs[2][2] = {{0u, 0u}, {0u, 0u}};          // rowsum MMA accumulators

#pragma unroll
    for (int it = 0; it < 16; it++) {
        int n0 = it * 16;
        uint32_t bq[4];
        {
            int h = (lane & 7) + 8 * ((lane >> 3) & 1);
            int n = n0 + 8 * (lane >> 4);
            ldsm_x4t(bq, sP + h * 512 + (((n >> 3) ^ (h & 7)) << 4));
        }
        __half2 cp0 = zero2, cp1 = zero2;
#pragma unroll
        for (int mf = 0; mf < 2; mf++) {
            uint32_t d0[2], d1[2];
            mma_h16(d0, a[mf], bq[0], bq[1]);          // cols n0 + 2q
            mma_h16(d1, a[mf], bq[2], bq[3]);          // cols n0 + 8 + 2q
            uint32_t t[4];                             // tanh, in A-fragment layout
            t[0] = tanh_h2u(d0[0]);
            t[1] = tanh_h2u(d0[1]);
            t[2] = tanh_h2u(d1[0]);
            t[3] = tanh_h2u(d1[1]);
            // row sums on tensor pipe: rs += T(m16k16) @ ones(k16n8)
            mma_h16_acc(rs[mf], t, ONES, ONES);
            // col partials (sum over this warp's 32 rows)
            cp0 = __hadd2(cp0, __hadd2(*(__half2*)&t[0], *(__half2*)&t[1]));
            cp1 = __hadd2(cp1, __hadd2(*(__half2*)&t[2], *(__half2*)&t[3]));
        }
        cp0 = __hadd2(cp0, shfl_h2(cp0, 4));
        cp0 = __hadd2(cp0, shfl_h2(cp0, 8));
        cp0 = __hadd2(cp0, shfl_h2(cp0, 16));
        cp1 = __hadd2(cp1, shfl_h2(cp1, 4));
        cp1 = __hadd2(cp1, shfl_h2(cp1, 8));
        cp1 = __hadd2(cp1, shfl_h2(cp1, 16));
        if (lane < 4) {
            colpart[w][(n0 >> 1) + lane]     = cp0;
            colpart[w][(n0 >> 1) + 4 + lane] = cp1;
        }
    }

    // rowsum extraction: rs[mf] c0 holds rowsum(row) in every column pair
    if ((lane & 3) == 0) {
#pragma unroll
        for (int mf = 0; mf < 2; mf++) {
            int row = w * 32 + mf * 16 + (lane >> 2);
            rowsum[row]     = __low2float(*(__half2*)&rs[mf][0]);
            rowsum[row + 8] = __low2float(*(__half2*)&rs[mf][1]);
        }
    }
    __syncthreads();

    size_t o = (size_t)b * DEF + tid;
    out[o] = drug[o] * tanh_fast(rowsum[tid]);

    if (tid < 128) {
        float c0 = 0.0f, c1 = 0.0f;
#pragma unroll
        for (int ww = 0; ww < 8; ww++) {
            __half2 v = colpart[ww][tid];
            c0 += __low2float(v);
            c1 += __high2float(v);
        }
        size_t base2 = (size_t)BSZ * DEF + (size_t)b * DEF + 2 * tid;
        out[base2]     = protein[(size_t)b * DEF + 2 * tid]     * tanh_fast(c0);
        out[base2 + 1] = protein[(size_t)b * DEF + 2 * tid + 1] * tanh_fast(c1);
    }
}

// ---------------------------------------------------------------------------
extern "C" void kernel_launch(void* const* d_in, const int* in_sizes, int n_in,
                              void* d_out, int out_size)
{
    const float* drug    = (const float*)d_in[0];
    const float* protein = (const float*)d_in[1];
    const float* W_d     = (const float*)d_in[2];
    const float* b_d     = (const float*)d_in[3];
    const float* W_p     = (const float*)d_in[4];
    const float* b_p     = (const float*)d_in[5];
    float* out = (float*)d_out;

    cudaFuncSetAttribute(gemm_tc_kernel, cudaFuncAttributeMaxDynamicSharedMemorySize, GSMEM);

    prep_kernel<<<3072, 256>>>(drug, protein, W_d, W_p);
    gemm_tc_kernel<<<dim3(NF / 256, BSZ / 128, 2), 256, GSMEM>>>(b_d, b_p);
    interact_kernel<<<BSZ, 256>>>(drug, protein, out);
}

// round 10
// speedup vs baseline: 1.0506x; 1.0422x over previous
#include <cuda_runtime.h>
#include <cuda_fp16.h>
#include <cstdint>

#define DEF 256
#define NF  4096   // DEF * HEAD
#define BSZ 4096

// f16 scratch
__device__ __half g_abf[2][(size_t)BSZ * DEF];   // drug/protein f16
__device__ __half g_wbf[2][(size_t)NF * DEF];    // W transposed [n][k] f16 (W_d pre-scaled by 1/16)
__device__ __half g_att[2][(size_t)BSZ * NF];    // relu activations f16 (drug side pre-scaled)

// ---------------------------------------------------------------------------
// helpers
// ---------------------------------------------------------------------------
__device__ __forceinline__ float tanh_fast(float x) {
    float y;
    asm("tanh.approx.f32 %0, %1;" : "=f"(y) : "f"(x));
    return y;
}
__device__ __forceinline__ uint32_t tanh_h2u(uint32_t v) {
    uint32_t r;
    asm("tanh.approx.f16x2 %0, %1;" : "=r"(r) : "r"(v));
    return r;
}
__device__ __forceinline__ uint32_t smem_u32(const void* p) {
    uint32_t a;
    asm("{ .reg .u64 t; cvta.to.shared.u64 t, %1; cvt.u32.u64 %0, t; }" : "=r"(a) : "l"(p));
    return a;
}
__device__ __forceinline__ void cp16(uint32_t dst, const void* src) {
    asm volatile("cp.async.cg.shared.global [%0], [%1], 16;"
                 :: "r"(dst), "l"(__cvta_generic_to_global(src)) : "memory");
}
#define CP_COMMIT() asm volatile("cp.async.commit_group;" ::: "memory")
#define CP_WAIT(n)  asm volatile("cp.async.wait_group %0;" :: "n"(n) : "memory")

__device__ __forceinline__ void ldsm_x4(uint32_t (&r)[4], uint32_t addr) {
    asm volatile("ldmatrix.sync.aligned.m8n8.x4.shared.b16 {%0,%1,%2,%3}, [%4];"
                 : "=r"(r[0]), "=r"(r[1]), "=r"(r[2]), "=r"(r[3]) : "r"(addr));
}
__device__ __forceinline__ void ldsm_x4t(uint32_t (&r)[4], uint32_t addr) {
    asm volatile("ldmatrix.sync.aligned.m8n8.x4.trans.shared.b16 {%0,%1,%2,%3}, [%4];"
                 : "=r"(r[0]), "=r"(r[1]), "=r"(r[2]), "=r"(r[3]) : "r"(addr));
}
// f16 inputs, f16 accumulator, D += A*B
__device__ __forceinline__ void mma_h16_acc(uint32_t (&d)[2], const uint32_t (&a)[4],
                                            uint32_t b0, uint32_t b1) {
    asm volatile("mma.sync.aligned.m16n8k16.row.col.f16.f16.f16.f16 "
                 "{%0,%1}, {%2,%3,%4,%5}, {%6,%7}, {%0,%1};"
                 : "+r"(d[0]), "+r"(d[1])
                 : "r"(a[0]), "r"(a[1]), "r"(a[2]), "r"(a[3]), "r"(b0), "r"(b1));
}
// f16 inputs, f16 accumulator, D = A*B
__device__ __forceinline__ void mma_h16(uint32_t (&d)[2], const uint32_t (&a)[4],
                                        uint32_t b0, uint32_t b1) {
    asm volatile("mma.sync.aligned.m16n8k16.row.col.f16.f16.f16.f16 "
                 "{%0,%1}, {%2,%3,%4,%5}, {%6,%7}, {%8,%9};"
                 : "=r"(d[0]), "=r"(d[1])
                 : "r"(a[0]), "r"(a[1]), "r"(a[2]), "r"(a[3]),
                   "r"(b0), "r"(b1), "r"(0u), "r"(0u));
}
__device__ __forceinline__ __half2 shfl_h2(__half2 v, int m) {
    uint32_t u = *reinterpret_cast<uint32_t*>(&v);
    u = __shfl_xor_sync(0xffffffffu, u, m);
    return *reinterpret_cast<__half2*>(&u);
}

// ---------------------------------------------------------------------------
// Prep: blocks [0,1024): drug/protein fp32 -> f16
//       blocks [1024,3072): W[k][n] fp32 -> Wt[n][k] f16 (W_d scaled by 1/16)
// ---------------------------------------------------------------------------
__global__ __launch_bounds__(256) void prep_kernel(
    const float* __restrict__ drug, const float* __restrict__ protein,
    const float* __restrict__ Wd, const float* __restrict__ Wp)
{
    __shared__ float t[32][33];
    int bid = blockIdx.x, tid = threadIdx.x;
    if (bid < 1024) {
        int i = bid * 256 + tid;                      // < BSZ*DEF/4
        float4 v = ((const float4*)drug)[i];
        __half2* d0 = (__half2*)g_abf[0];
        d0[i * 2]     = __floats2half2_rn(v.x, v.y);
        d0[i * 2 + 1] = __floats2half2_rn(v.z, v.w);
        float4 w = ((const float4*)protein)[i];
        __half2* d1 = (__half2*)g_abf[1];
        d1[i * 2]     = __floats2half2_rn(w.x, w.y);
        d1[i * 2 + 1] = __floats2half2_rn(w.z, w.w);
        return;
    }
    int wb = bid - 1024;                              // 0..2047
    int z = wb >> 10;
    int r = wb & 1023;
    int n0 = (r & 127) * 32, k0 = (r >> 7) * 32;
    const float* W = z ? Wp : Wd;
    float scale = z ? 1.0f : 0.0625f;
    int tx = tid & 31, ty = tid >> 5;                 // (32, 8)
#pragma unroll
    for (int q = 0; q < 4; q++)
        t[ty + q * 8][tx] = W[(size_t)(k0 + ty + q * 8) * NF + n0 + tx];
    __syncthreads();
#pragma unroll
    for (int q = 0; q < 4; q++)
        g_wbf[z][(size_t)(n0 + ty + q * 8) * DEF + k0 + tx] =
            __float2half(t[tx][ty + q * 8] * scale);
}

// ---------------------------------------------------------------------------
// HMMA GEMM (f16 accumulators): g_att[z][128x128 tile] = relu(A@Wt^T + b)
// 256 thr (8 warps, warp tile 64x32). K = 4 chunks of 64, 2-stage cp.async
// pipeline, 64KB smem -> 2 CTAs/SM. Epilogue staged through smem (STG.128).
// (Proven R6 configuration.)
// ---------------------------------------------------------------------------
#define GSMEM 65536

__global__ __launch_bounds__(256, 2) void gemm_tc_kernel(const float* __restrict__ b_d,
                                                         const float* __restrict__ b_p)
{
    extern __shared__ __align__(16) char dsm[];       // stage s: A @ s*32768, B @ s*32768+16384
    __shared__ __half2 bias2[64];

    const int tid = threadIdx.x, lane = tid & 31, w = tid >> 5;
    const int wm = w >> 2, wn = w & 3;                // 2x4 warp grid
    const int Nb = blockIdx.x * 128, Mb = blockIdx.y * 128, z = blockIdx.z;
    uint32_t sbase = smem_u32(dsm);

    const __half* Ag = g_abf[z];
    const __half* Bg = g_wbf[z];
    if (tid < 64) {
        float s = z ? 1.0f : 0.0625f;
        const float* bias = z ? b_p : b_d;
        bias2[tid] = __floats2half2_rn(bias[Nb + 2 * tid] * s, bias[Nb + 2 * tid + 1] * s);
    }

    auto load_chunk = [&](int ch, int st) {
        uint32_t aB = sbase + st * 32768;
        uint32_t bB = aB + 16384;
#pragma unroll
        for (int j = 0; j < 4; j++) {
            int idx = tid + j * 256;                   // 0..1023
            int r = idx >> 3, c = idx & 7;
            uint32_t sw = (uint32_t)(r * 128 + ((c ^ (r & 7)) << 4));
            cp16(aB + sw, Ag + (size_t)(Mb + r) * DEF + ch * 64 + c * 8);
            cp16(bB + sw, Bg + (size_t)(Nb + r) * DEF + ch * 64 + c * 8);
        }
        CP_COMMIT();
    };

    load_chunk(0, 0);
    load_chunk(1, 1);

    uint32_t acc[4][4][2];
#pragma unroll
    for (int mf = 0; mf < 4; mf++)
#pragma unroll
        for (int nf = 0; nf < 4; nf++) { acc[mf][nf][0] = 0u; acc[mf][nf][1] = 0u; }

#pragma unroll
    for (int ch = 0; ch < 4; ch++) {
        if (ch == 3) { CP_WAIT(0); } else { CP_WAIT(1); }
        __syncthreads();
        uint32_t aBase = sbase + (ch & 1) * 32768;
        uint32_t bBase = aBase + 16384;
#pragma unroll
        for (int ks = 0; ks < 4; ks++) {
            uint32_t a[4][4];
#pragma unroll
            for (int mf = 0; mf < 4; mf++) {
                int r  = wm * 64 + mf * 16 + (lane & 7) + 8 * ((lane >> 3) & 1);
                int kc = ks * 2 + (lane >> 4);
                ldsm_x4(a[mf], aBase + r * 128 + ((kc ^ (r & 7)) << 4));
            }
            uint32_t bq[2][4];
#pragma unroll
            for (int g = 0; g < 2; g++) {
                int nr = wn * 32 + g * 16 + (lane & 7) + 8 * ((lane >> 4) & 1);
                int kc = ks * 2 + ((lane >> 3) & 1);
                ldsm_x4(bq[g], bBase + nr * 128 + ((kc ^ (nr & 7)) << 4));
            }
#pragma unroll
            for (int mf = 0; mf < 4; mf++)
#pragma unroll
                for (int nf = 0; nf < 4; nf++)
                    mma_h16_acc(acc[mf][nf], a[mf],
                                bq[nf >> 1][(nf & 1) * 2], bq[nf >> 1][(nf & 1) * 2 + 1]);
        }
        __syncthreads();
        if (ch + 2 < 4) load_chunk(ch + 2, ch & 1);
    }

    // epilogue: bias + relu in half2, staged via smem (XOR-swizzled), STG.128
    const __half2 z2 = __float2half2_rn(0.0f);
#pragma unroll
    for (int mf = 0; mf < 4; mf++) {
        int r0 = wm * 64 + mf * 16 + (lane >> 2);
#pragma unroll
        for (int nf = 0; nf < 4; nf++) {
            int u = wn * 4 + nf;                       // 16B unit within 256B row
            __half2 b2 = bias2[u * 4 + (lane & 3)];
            __half2 h0 = __hmax2(__hadd2(*(__half2*)&acc[mf][nf][0], b2), z2);
            __half2 h1 = __hmax2(__hadd2(*(__half2*)&acc[mf][nf][1], b2), z2);
            uint32_t a0 = sbase + r0 * 256 + ((u ^ (r0 & 7)) << 4) + 4 * (lane & 3);
            int r1 = r0 + 8;
            uint32_t a1 = sbase + r1 * 256 + ((u ^ (r1 & 7)) << 4) + 4 * (lane & 3);
            asm volatile("st.shared.b32 [%0], %1;" :: "r"(a0), "r"(*(uint32_t*)&h0) : "memory");
            asm volatile("st.shared.b32 [%0], %1;" :: "r"(a1), "r"(*(uint32_t*)&h1) : "memory");
        }
    }
    __syncthreads();
#pragma unroll
    for (int p = 0; p < 8; p++) {
        int g = tid + p * 256;                         // 0..2047 16B units
        int row = g >> 4, u = g & 15;
        uint4 v;
        uint32_t ad = sbase + row * 256 + ((u ^ (row & 7)) << 4);
        asm volatile("ld.shared.v4.u32 {%0,%1,%2,%3}, [%4];"
                     : "=r"(v.x), "=r"(v.y), "=r"(v.z), "=r"(v.w) : "r"(ad));
        *(uint4*)&g_att[z][(size_t)(Mb + row) * NF + Nb + u * 8] = v;
    }
}

// ---------------------------------------------------------------------------
// Interaction: per-sample S = D(scaled) @ P via f16-acc HMMA (K=16).
// Row sums computed ON THE TENSOR PIPE: tanh results (C-fragment layout ==
// A-fragment layout) feed a second MMA with B = ones. No L2 discards.
// ---------------------------------------------------------------------------
__global__ __launch_bounds__(256) void interact_kernel(
    const float* __restrict__ drug, const float* __restrict__ protein,
    float* __restrict__ out)
{
    __shared__ __align__(16) char Dsm[256 * 48];      // D rows stride 48B (32B data + pad)
    __shared__ __align__(16) char Psm[16 * 512];      // P [16][256] f16, XOR-swizzled
    __shared__ __half2 colpart[8][128];
    __shared__ float rowsum[256];

    const int b = blockIdx.x, tid = threadIdx.x, lane = tid & 31, w = tid >> 5;
    uint32_t sD = smem_u32(Dsm), sP = smem_u32(Psm);
    const __half* Drow = g_att[0] + (size_t)b * NF;
    const __half* Prow = g_att[1] + (size_t)b * NF;

#pragma unroll
    for (int j = 0; j < 2; j++) {
        int idx = tid + j * 256;                       // 0..511, 16B chunks
        int r = idx >> 1, c = idx & 1;
        cp16(sD + r * 48 + c * 16, Drow + idx * 8);
        int h = idx >> 5, c2 = idx & 31;
        cp16(sP + h * 512 + ((c2 ^ (h & 7)) << 4), Prow + idx * 8);
    }
    CP_COMMIT(); CP_WAIT(0); __syncthreads();

    uint32_t a[2][4];
#pragma unroll
    for (int mf = 0; mf < 2; mf++) {
        int r  = w * 32 + mf * 16 + (lane & 7) + 8 * ((lane >> 3) & 1);
        int kc = lane >> 4;
        ldsm_x4(a[mf], sD + r * 48 + kc * 16);
    }

    const uint32_t ONES = 0x3C003C00u;                 // (1.0h, 1.0h)
    const __half2 zero2 = __float2half2_rn(0.0f);
    uint32_t rs[2][2] = {{0u, 0u}, {0u, 0u}};          // rowsum MMA accumulators

#pragma unroll
    for (int it = 0; it < 16; it++) {
        int n0 = it * 16;
        uint32_t bq[4];
        {
            int h = (lane & 7) + 8 * ((lane >> 3) & 1);
            int n = n0 + 8 * (lane >> 4);
            ldsm_x4t(bq, sP + h * 512 + (((n >> 3) ^ (h & 7)) << 4));
        }
        __half2 cp0 = zero2, cp1 = zero2;
#pragma unroll
        for (int mf = 0; mf < 2; mf++) {
            uint32_t d0[2], d1[2];
            mma_h16(d0, a[mf], bq[0], bq[1]);          // cols n0 + 2q
            mma_h16(d1, a[mf], bq[2], bq[3]);          // cols n0 + 8 + 2q
            uint32_t t[4];                             // tanh, in A-fragment layout
            t[0] = tanh_h2u(d0[0]);
            t[1] = tanh_h2u(d0[1]);
            t[2] = tanh_h2u(d1[0]);
            t[3] = tanh_h2u(d1[1]);
            // row sums on tensor pipe: rs += T(m16k16) @ ones(k16n8)
            mma_h16_acc(rs[mf], t, ONES, ONES);
            // col partials (sum over this warp's 32 rows)
            cp0 = __hadd2(cp0, __hadd2(*(__half2*)&t[0], *(__half2*)&t[1]));
            cp1 = __hadd2(cp1, __hadd2(*(__half2*)&t[2], *(__half2*)&t[3]));
        }
        cp0 = __hadd2(cp0, shfl_h2(cp0, 4));
        cp0 = __hadd2(cp0, shfl_h2(cp0, 8));
        cp0 = __hadd2(cp0, shfl_h2(cp0, 16));
        cp1 = __hadd2(cp1, shfl_h2(cp1, 4));
        cp1 = __hadd2(cp1, shfl_h2(cp1, 8));
        cp1 = __hadd2(cp1, shfl_h2(cp1, 16));
        if (lane < 4) {
            colpart[w][(n0 >> 1) + lane]     = cp0;
            colpart[w][(n0 >> 1) + 4 + lane] = cp1;
        }
    }

    // rowsum extraction: rs[mf] col 0 holds rowsum(row) (all cols identical)
    if ((lane & 3) == 0) {
#pragma unroll
        for (int mf = 0; mf < 2; mf++) {
            int row = w * 32 + mf * 16 + (lane >> 2);
            rowsum[row]     = __low2float(*(__half2*)&rs[mf][0]);
            rowsum[row + 8] = __low2float(*(__half2*)&rs[mf][1]);
        }
    }
    __syncthreads();

    size_t o = (size_t)b * DEF + tid;
    out[o] = drug[o] * tanh_fast(rowsum[tid]);

    if (tid < 128) {
        float c0 = 0.0f, c1 = 0.0f;
#pragma unroll
        for (int ww = 0; ww < 8; ww++) {
            __half2 v = colpart[ww][tid];
            c0 += __low2float(v);
            c1 += __high2float(v);
        }
        size_t base2 = (size_t)BSZ * DEF + (size_t)b * DEF + 2 * tid;
        out[base2]     = protein[(size_t)b * DEF + 2 * tid]     * tanh_fast(c0);
        out[base2 + 1] = protein[(size_t)b * DEF + 2 * tid + 1] * tanh_fast(c1);
    }
}

// ---------------------------------------------------------------------------
extern "C" void kernel_launch(void* const* d_in, const int* in_sizes, int n_in,
                              void* d_out, int out_size)
{
    const float* drug    = (const float*)d_in[0];
    const float* protein = (const float*)d_in[1];
    const float* W_d     = (const float*)d_in[2];
    const float* b_d     = (const float*)d_in[3];
    const float* W_p     = (const float*)d_in[4];
    const float* b_p     = (const float*)d_in[5];
    float* out = (float*)d_out;

    cudaFuncSetAttribute(gemm_tc_kernel, cudaFuncAttributeMaxDynamicSharedMemorySize, GSMEM);

    prep_kernel<<<3072, 256>>>(drug, protein, W_d, W_p);
    gemm_tc_kernel<<<dim3(NF / 128, BSZ / 128, 2), 256, GSMEM>>>(b_d, b_p);
    interact_kernel<<<BSZ, 256>>>(drug, protein, out);
}

// round 11
// speedup vs baseline: 1.0871x; 1.0347x over previous
#include <cuda_runtime.h>
#include <cuda_fp16.h>
#include <cstdint>

#define DEF 256
#define NF  4096   // DEF * HEAD
#define BSZ 4096

// f16 scratch
__device__ __half g_abf[2][(size_t)BSZ * DEF];   // drug/protein f16
__device__ __half g_wbf[2][(size_t)NF * DEF];    // W transposed [n][k] f16 (W_d pre-scaled by 1/16)
__device__ __half g_att[2][(size_t)BSZ * NF];    // relu activations f16 (drug side pre-scaled)

// ---------------------------------------------------------------------------
// helpers
// ---------------------------------------------------------------------------
__device__ __forceinline__ float tanh_fast(float x) {
    float y;
    asm("tanh.approx.f32 %0, %1;" : "=f"(y) : "f"(x));
    return y;
}
__device__ __forceinline__ uint32_t tanh_h2u(uint32_t v) {
    uint32_t r;
    asm("tanh.approx.f16x2 %0, %1;" : "=r"(r) : "r"(v));
    return r;
}
__device__ __forceinline__ uint32_t smem_u32(const void* p) {
    uint32_t a;
    asm("{ .reg .u64 t; cvta.to.shared.u64 t, %1; cvt.u32.u64 %0, t; }" : "=r"(a) : "l"(p));
    return a;
}
__device__ __forceinline__ void cp16(uint32_t dst, const void* src) {
    asm volatile("cp.async.cg.shared.global [%0], [%1], 16;"
                 :: "r"(dst), "l"(__cvta_generic_to_global(src)) : "memory");
}
#define CP_COMMIT() asm volatile("cp.async.commit_group;" ::: "memory")
#define CP_WAIT(n)  asm volatile("cp.async.wait_group %0;" :: "n"(n) : "memory")

__device__ __forceinline__ void ldsm_x4(uint32_t (&r)[4], uint32_t addr) {
    asm volatile("ldmatrix.sync.aligned.m8n8.x4.shared.b16 {%0,%1,%2,%3}, [%4];"
                 : "=r"(r[0]), "=r"(r[1]), "=r"(r[2]), "=r"(r[3]) : "r"(addr));
}
__device__ __forceinline__ void ldsm_x4t(uint32_t (&r)[4], uint32_t addr) {
    asm volatile("ldmatrix.sync.aligned.m8n8.x4.trans.shared.b16 {%0,%1,%2,%3}, [%4];"
                 : "=r"(r[0]), "=r"(r[1]), "=r"(r[2]), "=r"(r[3]) : "r"(addr));
}
// f16 inputs, f16 accumulator, D += A*B
__device__ __forceinline__ void mma_h16_acc(uint32_t (&d)[2], const uint32_t (&a)[4],
                                            uint32_t b0, uint32_t b1) {
    asm volatile("mma.sync.aligned.m16n8k16.row.col.f16.f16.f16.f16 "
                 "{%0,%1}, {%2,%3,%4,%5}, {%6,%7}, {%0,%1};"
                 : "+r"(d[0]), "+r"(d[1])
                 : "r"(a[0]), "r"(a[1]), "r"(a[2]), "r"(a[3]), "r"(b0), "r"(b1));
}
// f16 inputs, f16 accumulator, D = A*B
__device__ __forceinline__ void mma_h16(uint32_t (&d)[2], const uint32_t (&a)[4],
                                        uint32_t b0, uint32_t b1) {
    asm volatile("mma.sync.aligned.m16n8k16.row.col.f16.f16.f16.f16 "
                 "{%0,%1}, {%2,%3,%4,%5}, {%6,%7}, {%8,%9};"
                 : "=r"(d[0]), "=r"(d[1])
                 : "r"(a[0]), "r"(a[1]), "r"(a[2]), "r"(a[3]),
                   "r"(b0), "r"(b1), "r"(0u), "r"(0u));
}
__device__ __forceinline__ __half2 shfl_h2(__half2 v, int m) {
    uint32_t u = *reinterpret_cast<uint32_t*>(&v);
    u = __shfl_xor_sync(0xffffffffu, u, m);
    return *reinterpret_cast<__half2*>(&u);
}

// ---------------------------------------------------------------------------
// Prep: blocks [0,1024): drug/protein fp32 -> f16
//       blocks [1024,3072): W[k][n] fp32 -> Wt[n][k] f16 (W_d scaled by 1/16)
// ---------------------------------------------------------------------------
__global__ __launch_bounds__(256) void prep_kernel(
    const float* __restrict__ drug, const float* __restrict__ protein,
    const float* __restrict__ Wd, const float* __restrict__ Wp)
{
    __shared__ float t[32][33];
    int bid = blockIdx.x, tid = threadIdx.x;
    if (bid < 1024) {
        int i = bid * 256 + tid;                      // < BSZ*DEF/4
        float4 v = ((const float4*)drug)[i];
        __half2* d0 = (__half2*)g_abf[0];
        d0[i * 2]     = __floats2half2_rn(v.x, v.y);
        d0[i * 2 + 1] = __floats2half2_rn(v.z, v.w);
        float4 w = ((const float4*)protein)[i];
        __half2* d1 = (__half2*)g_abf[1];
        d1[i * 2]     = __floats2half2_rn(w.x, w.y);
        d1[i * 2 + 1] = __floats2half2_rn(w.z, w.w);
        return;
    }
    int wb = bid - 1024;                              // 0..2047
    int z = wb >> 10;
    int r = wb & 1023;
    int n0 = (r & 127) * 32, k0 = (r >> 7) * 32;
    const float* W = z ? Wp : Wd;
    float scale = z ? 1.0f : 0.0625f;
    int tx = tid & 31, ty = tid >> 5;                 // (32, 8)
#pragma unroll
    for (int q = 0; q < 4; q++)
        t[ty + q * 8][tx] = W[(size_t)(k0 + ty + q * 8) * NF + n0 + tx];
    __syncthreads();
#pragma unroll
    for (int q = 0; q < 4; q++)
        g_wbf[z][(size_t)(n0 + ty + q * 8) * DEF + k0 + tx] =
            __float2half(t[tx][ty + q * 8] * scale);
}

// ---------------------------------------------------------------------------
// HMMA GEMM (f16 acc): CTA tile 128x128, 128 threads (4 warps, 2x2 grid),
// warp tile 64x64 -> 8 LDSM per 32 MMA. K = 4 chunks of 64, 2-stage cp.async,
// 64KB smem, 3 CTAs/SM. Epilogue staged through smem, STG.128.
// ---------------------------------------------------------------------------
#define GSMEM 65536

__global__ __launch_bounds__(128, 3) void gemm_tc_kernel(const float* __restrict__ b_d,
                                                         const float* __restrict__ b_p)
{
    extern __shared__ __align__(16) char dsm[];       // stage s: A @ s*32768, B @ s*32768+16384
    __shared__ __half2 bias2[64];

    const int tid = threadIdx.x, lane = tid & 31, w = tid >> 5;
    const int wm = w >> 1, wn = w & 1;                // 2x2 warp grid
    const int Nb = blockIdx.x * 128, Mb = blockIdx.y * 128, z = blockIdx.z;
    uint32_t sbase = smem_u32(dsm);

    const __half* Ag = g_abf[z];
    const __half* Bg = g_wbf[z];
    if (tid < 64) {
        float s = z ? 1.0f : 0.0625f;
        const float* bias = z ? b_p : b_d;
        bias2[tid] = __floats2half2_rn(bias[Nb + 2 * tid] * s, bias[Nb + 2 * tid + 1] * s);
    }

    auto load_chunk = [&](int ch, int st) {
        uint32_t aB = sbase + st * 32768;
        uint32_t bB = aB + 16384;
#pragma unroll
        for (int j = 0; j < 8; j++) {
            int idx = tid + j * 128;                   // 0..1023
            int r = idx >> 3, c = idx & 7;
            uint32_t sw = (uint32_t)(r * 128 + ((c ^ (r & 7)) << 4));
            cp16(aB + sw, Ag + (size_t)(Mb + r) * DEF + ch * 64 + c * 8);
            cp16(bB + sw, Bg + (size_t)(Nb + r) * DEF + ch * 64 + c * 8);
        }
        CP_COMMIT();
    };

    load_chunk(0, 0);
    load_chunk(1, 1);

    uint32_t acc[4][8][2];
#pragma unroll
    for (int mf = 0; mf < 4; mf++)
#pragma unroll
        for (int nf = 0; nf < 8; nf++) { acc[mf][nf][0] = 0u; acc[mf][nf][1] = 0u; }

#pragma unroll
    for (int ch = 0; ch < 4; ch++) {
        if (ch == 3) { CP_WAIT(0); } else { CP_WAIT(1); }
        __syncthreads();
        uint32_t aBase = sbase + (ch & 1) * 32768;
        uint32_t bBase = aBase + 16384;
#pragma unroll
        for (int ks = 0; ks < 4; ks++) {
            uint32_t a[4][4];
#pragma unroll
            for (int mf = 0; mf < 4; mf++) {
                int r  = wm * 64 + mf * 16 + (lane & 7) + 8 * ((lane >> 3) & 1);
                int kc = ks * 2 + (lane >> 4);
                ldsm_x4(a[mf], aBase + r * 128 + ((kc ^ (r & 7)) << 4));
            }
            uint32_t bq[4][4];
#pragma unroll
            for (int g = 0; g < 4; g++) {
                int nr = wn * 64 + g * 16 + (lane & 7) + 8 * ((lane >> 4) & 1);
                int kc = ks * 2 + ((lane >> 3) & 1);
                ldsm_x4(bq[g], bBase + nr * 128 + ((kc ^ (nr & 7)) << 4));
            }
#pragma unroll
            for (int mf = 0; mf < 4; mf++)
#pragma unroll
                for (int nf = 0; nf < 8; nf++)
                    mma_h16_acc(acc[mf][nf], a[mf],
                                bq[nf >> 1][(nf & 1) * 2], bq[nf >> 1][(nf & 1) * 2 + 1]);
        }
        __syncthreads();
        if (ch + 2 < 4) load_chunk(ch + 2, ch & 1);
    }

    // epilogue: bias + relu in half2, staged via smem (XOR-swizzled), STG.128
    const __half2 z2 = __float2half2_rn(0.0f);
#pragma unroll
    for (int mf = 0; mf < 4; mf++) {
        int r0 = wm * 64 + mf * 16 + (lane >> 2);
        int r1 = r0 + 8;
#pragma unroll
        for (int nf = 0; nf < 8; nf++) {
            int u = wn * 8 + nf;                       // 16B unit within 256B row (0..15)
            __half2 b2 = bias2[u * 4 + (lane & 3)];
            __half2 h0 = __hmax2(__hadd2(*(__half2*)&acc[mf][nf][0], b2), z2);
            __half2 h1 = __hmax2(__hadd2(*(__half2*)&acc[mf][nf][1], b2), z2);
            uint32_t a0 = sbase + r0 * 256 + ((u ^ (r0 & 7)) << 4) + 4 * (lane & 3);
            uint32_t a1 = sbase + r1 * 256 + ((u ^ (r1 & 7)) << 4) + 4 * (lane & 3);
            asm volatile("st.shared.b32 [%0], %1;" :: "r"(a0), "r"(*(uint32_t*)&h0) : "memory");
            asm volatile("st.shared.b32 [%0], %1;" :: "r"(a1), "r"(*(uint32_t*)&h1) : "memory");
        }
    }
    __syncthreads();
#pragma unroll
    for (int p = 0; p < 16; p++) {
        int g = tid + p * 128;                         // 0..2047 16B units
        int row = g >> 4, u = g & 15;
        uint4 v;
        uint32_t ad = sbase + row * 256 + ((u ^ (row & 7)) << 4);
        asm volatile("ld.shared.v4.u32 {%0,%1,%2,%3}, [%4];"
                     : "=r"(v.x), "=r"(v.y), "=r"(v.z), "=r"(v.w) : "r"(ad));
        *(uint4*)&g_att[z][(size_t)(Mb + row) * NF + Nb + u * 8] = v;
    }
}

// ---------------------------------------------------------------------------
// Interaction: per-sample S = D(scaled) @ P via f16-acc HMMA (K=16).
// Row sums on the tensor pipe (tanh C-frag reinterpreted as A-frag, B=ones).
// ---------------------------------------------------------------------------
__global__ __launch_bounds__(256) void interact_kernel(
    const float* __restrict__ drug, const float* __restrict__ protein,
    float* __restrict__ out)
{
    __shared__ __align__(16) char Dsm[256 * 48];      // D rows stride 48B (32B data + pad)
    __shared__ __align__(16) char Psm[16 * 512];      // P [16][256] f16, XOR-swizzled
    __shared__ __half2 colpart[8][128];
    __shared__ float rowsum[256];

    const int b = blockIdx.x, tid = threadIdx.x, lane = tid & 31, w = tid >> 5;
    uint32_t sD = smem_u32(Dsm), sP = smem_u32(Psm);
    const __half* Drow = g_att[0] + (size_t)b * NF;
    const __half* Prow = g_att[1] + (size_t)b * NF;

#pragma unroll
    for (int j = 0; j < 2; j++) {
        int idx = tid + j * 256;                       // 0..511, 16B chunks
        int r = idx >> 1, c = idx & 1;
        cp16(sD + r * 48 + c * 16, Drow + idx * 8);
        int h = idx >> 5, c2 = idx & 31;
        cp16(sP + h * 512 + ((c2 ^ (h & 7)) << 4), Prow + idx * 8);
    }
    CP_COMMIT(); CP_WAIT(0); __syncthreads();

    uint32_t a[2][4];
#pragma unroll
    for (int mf = 0; mf < 2; mf++) {
        int r  = w * 32 + mf * 16 + (lane & 7) + 8 * ((lane >> 3) & 1);
        int kc = lane >> 4;
        ldsm_x4(a[mf], sD + r * 48 + kc * 16);
    }

    const uint32_t ONES = 0x3C003C00u;                 // (1.0h, 1.0h)
    const __half2 zero2 = __float2half2_rn(0.0f);
    uint32_t rs[2][2] = {{0u, 0u}, {0u, 0u}};          // rowsum MMA accumulators

#pragma unroll
    for (int it = 0; it < 16; it++) {
        int n0 = it * 16;
        uint32_t bq[4];
        {
            int h = (lane & 7) + 8 * ((lane >> 3) & 1);
            int n = n0 + 8 * (lane >> 4);
            ldsm_x4t(bq, sP + h * 512 + (((n >> 3) ^ (h & 7)) << 4));
        }
        __half2 cp0 = zero2, cp1 = zero2;
#pragma unroll
        for (int mf = 0; mf < 2; mf++) {
            uint32_t d0[2], d1[2];
            mma_h16(d0, a[mf], bq[0], bq[1]);          // cols n0 + 2q
            mma_h16(d1, a[mf], bq[2], bq[3]);          // cols n0 + 8 + 2q
            uint32_t t[4];                             // tanh, in A-fragment layout
            t[0] = tanh_h2u(d0[0]);
            t[1] = tanh_h2u(d0[1]);
            t[2] = tanh_h2u(d1[0]);
            t[3] = tanh_h2u(d1[1]);
            // row sums on tensor pipe: rs += T(m16k16) @ ones(k16n8)
            mma_h16_acc(rs[mf], t, ONES, ONES);
            // col partials (sum over this warp's 32 rows)
            cp0 = __hadd2(cp0, __hadd2(*(__half2*)&t[0], *(__half2*)&t[1]));
            cp1 = __hadd2(cp1, __hadd2(*(__half2*)&t[2], *(__half2*)&t[3]));
        }
        cp0 = __hadd2(cp0, shfl_h2(cp0, 4));
        cp0 = __hadd2(cp0, shfl_h2(cp0, 8));
        cp0 = __hadd2(cp0, shfl_h2(cp0, 16));
        cp1 = __hadd2(cp1, shfl_h2(cp1, 4));
        cp1 = __hadd2(cp1, shfl_h2(cp1, 8));
        cp1 = __hadd2(cp1, shfl_h2(cp1, 16));
        if (lane < 4) {
            colpart[w][(n0 >> 1) + lane]     = cp0;
            colpart[w][(n0 >> 1) + 4 + lane] = cp1;
        }
    }

    // rowsum extraction: rs[mf] col 0 holds rowsum(row) (all cols identical)
    if ((lane & 3) == 0) {
#pragma unroll
        for (int mf = 0; mf < 2; mf++) {
            int row = w * 32 + mf * 16 + (lane >> 2);
            rowsum[row]     = __low2float(*(__half2*)&rs[mf][0]);
            rowsum[row + 8] = __low2float(*(__half2*)&rs[mf][1]);
        }
    }
    __syncthreads();

    size_t o = (size_t)b * DEF + tid;
    out[o] = drug[o] * tanh_fast(rowsum[tid]);

    if (tid < 128) {
        float c0 = 0.0f, c1 = 0.0f;
#pragma unroll
        for (int ww = 0; ww < 8; ww++) {
            __half2 v = colpart[ww][tid];
            c0 += __low2float(v);
            c1 += __high2float(v);
        }
        size_t base2 = (size_t)BSZ * DEF + (size_t)b * DEF + 2 * tid;
        out[base2]     = protein[(size_t)b * DEF + 2 * tid]     * tanh_fast(c0);
        out[base2 + 1] = protein[(size_t)b * DEF + 2 * tid + 1] * tanh_fast(c1);
    }
}

// ---------------------------------------------------------------------------
extern "C" void kernel_launch(void* const* d_in, const int* in_sizes, int n_in,
                              void* d_out, int out_size)
{
    const float* drug    = (const float*)d_in[0];
    const float* protein = (const float*)d_in[1];
    const float* W_d     = (const float*)d_in[2];
    const float* b_d     = (const float*)d_in[3];
    const float* W_p     = (const float*)d_in[4];
    const float* b_p     = (const float*)d_in[5];
    float* out = (float*)d_out;

    cudaFuncSetAttribute(gemm_tc_kernel, cudaFuncAttributeMaxDynamicSharedMemorySize, GSMEM);

    prep_kernel<<<3072, 256>>>(drug, protein, W_d, W_p);
    gemm_tc_kernel<<<dim3(NF / 128, BSZ / 128, 2), 128, GSMEM>>>(b_d, b_p);
    interact_kernel<<<BSZ, 256>>>(drug, protein, out);
}